// round 17
// baseline (speedup 1.0000x reference)
#include <cuda_runtime.h>
#include <cuda_bf16.h>
#include <mma.h>
#include <cstdint>

using namespace nvcuda;

// Problem dims
#define NB    8
#define NMAT  256
#define N3    64
#define NF    33
#define NPLANE (NMAT * NMAT)       // 65536
#define NTUBES (NB * NPLANE)       // 524288
#define NFP    (NB * NF)           // 264
#define PLSZ   ((size_t)NFP * NPLANE)

// Operand arrays, planar [6][plane][256][256] bf16 (hi/lo pairs):
//  A side: {0,1}=Ar  {2,3}=Ar+Ai  {4,5}=Ai-Ar
//  B side: {0,1}=Br+Bi  {2,3}=-Bi  {4,5}=Br
__device__ static __nv_bfloat16 g_A[6][PLSZ];
__device__ static __nv_bfloat16 g_B[6][PLSZ];
__device__ static float g_Cre[PLSZ];
__device__ static float g_Cim[PLSZ];

// ---------------------------------------------------------------------------
__device__ constexpr float TW32R[16] = {
    1.0f, 0.980785280403230449f, 0.923879532511286756f, 0.831469612302545237f,
    0.707106781186547524f, 0.555570233019602225f, 0.382683432365089772f,
    0.195090322016128268f, 0.0f, -0.195090322016128268f, -0.382683432365089772f,
    -0.555570233019602225f, -0.707106781186547524f, -0.831469612302545237f,
    -0.923879532511286756f, -0.980785280403230449f };
__device__ constexpr float TW32I[16] = {
    0.0f, 0.195090322016128268f, 0.382683432365089772f, 0.555570233019602225f,
    0.707106781186547524f, 0.831469612302545237f, 0.923879532511286756f,
    0.980785280403230449f, 1.0f, 0.980785280403230449f, 0.923879532511286756f,
    0.831469612302545237f, 0.707106781186547524f, 0.555570233019602225f,
    0.382683432365089772f, 0.195090322016128268f };
__device__ constexpr float W64R[33] = {
    1.0f, 0.995184726672196886f, 0.980785280403230449f, 0.956940335732208865f,
    0.923879532511286756f, 0.881921264348355030f, 0.831469612302545237f,
    0.773010453362736961f, 0.707106781186547524f, 0.634393284163645498f,
    0.555570233019602225f, 0.471396736825997649f, 0.382683432365089772f,
    0.290284677254462368f, 0.195090322016128268f, 0.098017140329560602f,
    0.0f, -0.098017140329560602f, -0.195090322016128268f, -0.290284677254462368f,
    -0.382683432365089772f, -0.471396736825997649f, -0.555570233019602225f,
    -0.634393284163645498f, -0.707106781186547524f, -0.773010453362736961f,
    -0.831469612302545237f, -0.881921264348355030f, -0.923879532511286756f,
    -0.956940335732208865f, -0.980785280403230449f, -0.995184726672196886f, -1.0f };
__device__ constexpr float W64I[33] = {
    0.0f, 0.098017140329560602f, 0.195090322016128268f, 0.290284677254462368f,
    0.382683432365089772f, 0.471396736825997649f, 0.555570233019602225f,
    0.634393284163645498f, 0.707106781186547524f, 0.773010453362736961f,
    0.831469612302545237f, 0.881921264348355030f, 0.923879532511286756f,
    0.956940335732208865f, 0.980785280403230449f, 0.995184726672196886f,
    1.0f, 0.995184726672196886f, 0.980785280403230449f, 0.956940335732208865f,
    0.923879532511286756f, 0.881921264348355030f, 0.831469612302545237f,
    0.773010453362736961f, 0.707106781186547524f, 0.634393284163645498f,
    0.555570233019602225f, 0.471396736825997649f, 0.382683432365089772f,
    0.290284677254462368f, 0.195090322016128268f, 0.098017140329560602f, 0.0f };
__device__ constexpr int BR5[32] = {
    0,16,8,24,4,20,12,28,2,18,10,26,6,22,14,30,
    1,17,9,25,5,21,13,29,3,19,11,27,7,23,15,31 };

template<int M, int SIGN>
static __device__ __forceinline__ void fft32_stage(float* zr, float* zi) {
    constexpr int H = M / 2;
#pragma unroll
    for (int g = 0; g < 32; g += M)
#pragma unroll
        for (int j = 0; j < H; ++j) {
            const float wr = TW32R[j * (32 / M)];
            const float wi = SIGN * TW32I[j * (32 / M)];
            const int i0 = g + j, i1 = g + j + H;
            const float ar = zr[i0], ai = zi[i0];
            const float br_ = zr[i1], bi = zi[i1];
            zr[i0] = ar + br_;  zi[i0] = ai + bi;
            const float dr = ar - br_, di = ai - bi;
            zr[i1] = dr * wr - di * wi;
            zi[i1] = dr * wi + di * wr;
        }
}
template<int SIGN>
static __device__ __forceinline__ void fft32(float* zr, float* zi) {
    fft32_stage<32, SIGN>(zr, zi);
    fft32_stage<16, SIGN>(zr, zi);
    fft32_stage<8,  SIGN>(zr, zi);
    fft32_stage<4,  SIGN>(zr, zi);
    fft32_stage<2,  SIGN>(zr, zi);
}

// ===========================================================================
// Forward rfft64; writes 6 planar bf16 operand arrays (Knuth 3M form).
// ===========================================================================
__global__ __launch_bounds__(128) void fft_fwd_kernel(const float* __restrict__ x, int sel)
{
    __shared__ float sx[128][N3 + 1];
    const int tid = threadIdx.x;

    const float* src = x + (size_t)blockIdx.x * 128 * N3;
    for (int i = tid; i < 128 * N3; i += 128)
        sx[i >> 6][i & 63] = src[i];
    __syncthreads();

    float zr[32], zi[32];
#pragma unroll
    for (int n = 0; n < 32; ++n) {
        zr[n] = sx[tid][2 * n];
        zi[n] = sx[tid][2 * n + 1];
    }
    fft32<-1>(zr, zi);

    const int tube = blockIdx.x * 128 + tid;
    const int b  = tube >> 16;
    const int ij = tube & 0xFFFF;

#pragma unroll
    for (int k = 0; k <= 32; ++k) {
        float Xr, Xi;
        if (k == 0 || k == 32) {
            const float e = zr[0], o = zi[0];
            Xr = (k == 0) ? (e + o) : (e - o);
            Xi = 0.0f;
        } else {
            const float Zkr = zr[BR5[k]],             Zki = zi[BR5[k]];
            const float Zcr = zr[BR5[(32 - k) & 31]], Zci = -zi[BR5[(32 - k) & 31]];
            const float Er = 0.5f * (Zkr + Zcr), Ei = 0.5f * (Zki + Zci);
            const float Dr = 0.5f * (Zkr - Zcr), Di = 0.5f * (Zki - Zci);
            const float Or = Di, Oi = -Dr;
            Xr = Er + W64R[k] * Or + W64I[k] * Oi;
            Xi = Ei + W64R[k] * Oi - W64I[k] * Or;
        }

        float v0, v1, v2;
        if (sel == 0) { v0 = Xr;      v1 = Xr + Xi; v2 = Xi - Xr; }  // Ar, Ar+Ai, Ai-Ar
        else          { v0 = Xr + Xi; v1 = -Xi;     v2 = Xr;      }  // Br+Bi, -Bi, Br

        const size_t off = (((size_t)(b * NF + k)) << 16) + ij;
        const __nv_bfloat16 h0 = __float2bfloat16(v0);
        const __nv_bfloat16 h1 = __float2bfloat16(v1);
        const __nv_bfloat16 h2 = __float2bfloat16(v2);
        const __nv_bfloat16 l0 = __float2bfloat16(v0 - __bfloat162float(h0));
        const __nv_bfloat16 l1 = __float2bfloat16(v1 - __bfloat162float(h1));
        const __nv_bfloat16 l2 = __float2bfloat16(v2 - __bfloat162float(h2));

        if (sel == 0) {
            g_A[0][off] = h0; g_A[1][off] = l0;
            g_A[2][off] = h1; g_A[3][off] = l1;
            g_A[4][off] = h2; g_A[5][off] = l2;
        } else {
            g_B[0][off] = h0; g_B[1][off] = l0;
            g_B[2][off] = h1; g_B[3][off] = l1;
            g_B[4][off] = h2; g_B[5][off] = l2;
        }
    }
}

// ===========================================================================
// Knuth-3M complex GEMM, bf16 wmma, 3 K-passes in one 48-chunk loop.
// CTA 128m x 128c, 256 threads (8 warps @ 64x32), 3-stage cp.async.
//   pass0: acc  = P1 = Ar*(Br+Bi)        (copy acc->acc2 after pass0)
//   pass1: acc += (Ar+Ai)*(-Bi)  -> Cre  (stored after chunk 31)
//   pass2: acc2 += (Ai-Ar)*Br    -> Cim
// ===========================================================================
#define CP_ASYNC16(dst, src) \
    asm volatile("cp.async.cg.shared.global [%0], [%1], 16;" :: "r"(dst), "l"(src) : "memory")
#define CP_COMMIT() asm volatile("cp.async.commit_group;" ::: "memory")
#define CP_WAIT1()  asm volatile("cp.async.wait_group 1;" ::: "memory")
#define CP_WAIT0()  asm volatile("cp.async.wait_group 0;" ::: "memory")

#define A_LDM 24
#define B_LDM 136
#define OF_B   (2 * 128 * A_LDM * 2)             // 12288 B: A block (2 arrays)
#define STG_BYTES (OF_B + 2 * 16 * B_LDM * 2)    // + 8704 = 20992
#define SMEM_GEMM (3 * STG_BYTES)                // 62976

typedef wmma::fragment<wmma::accumulator, 16, 16, 16, float> AccFrag;
typedef wmma::fragment<wmma::matrix_a, 16, 16, 16, __nv_bfloat16, wmma::row_major> AFrag;
typedef wmma::fragment<wmma::matrix_b, 16, 16, 16, __nv_bfloat16, wmma::row_major> BFrag;

__global__ __launch_bounds__(256) void cgemm_wmma_kernel()
{
    extern __shared__ char sm[];

    const int p  = blockIdx.z;
    const int m0 = blockIdx.x * 128;
    const int n0 = blockIdx.y * 128;
    const size_t pb = ((size_t)p) << 16;

    const int tid = threadIdx.x;
    const int wid = tid >> 5;
    const int wm  = wid & 1;        // 2 m-slots of 64
    const int wn  = wid >> 1;       // 4 n-slots of 32

    const uint32_t base = (uint32_t)__cvta_generic_to_shared(sm);

    // cp.async thread mapping (per array): A: row=tid>>1, half=tid&1; B: row=tid>>4, cb=tid&15
    const int arow = tid >> 1, ahalf = tid & 1;
    const int brow = tid >> 4, bcb   = tid & 15;

#define LOAD_CHUNK(st, cc) do {                                                        \
        const int _pass = (cc) >> 4;                                                   \
        const int _k0   = ((cc) & 15) << 4;                                            \
        const uint32_t _sb = base + (uint32_t)(st) * STG_BYTES;                        \
        _Pragma("unroll")                                                              \
        for (int _a = 0; _a < 2; ++_a) {                                               \
            CP_ASYNC16(_sb + (uint32_t)(_a * 128 * A_LDM + arow * A_LDM + ahalf * 8) * 2, \
                       &g_A[2 * _pass + _a][pb + (size_t)(m0 + arow) * 256 + _k0 + ahalf * 8]); \
            CP_ASYNC16(_sb + OF_B + (uint32_t)(_a * 16 * B_LDM + brow * B_LDM + bcb * 8) * 2,   \
                       &g_B[2 * _pass + _a][pb + (size_t)(_k0 + brow) * 256 + n0 + bcb * 8]);   \
        }                                                                              \
        CP_COMMIT();                                                                   \
    } while (0)

    AccFrag acc[4][2], acc2[4][2];
#pragma unroll
    for (int fm = 0; fm < 4; ++fm)
#pragma unroll
        for (int fn = 0; fn < 2; ++fn)
            wmma::fill_fragment(acc[fm][fn], 0.0f);

    LOAD_CHUNK(0, 0);
    LOAD_CHUNK(1, 1);

    for (int cc = 0; cc < 48; ++cc) {
        const int st = cc % 3;
        if (cc == 47) { CP_WAIT0(); } else { CP_WAIT1(); }
        __syncthreads();

        const char* stg = sm + st * STG_BYTES;
        const __nv_bfloat16* Ab = reinterpret_cast<const __nv_bfloat16*>(stg);
        const __nv_bfloat16* Bb = reinterpret_cast<const __nv_bfloat16*>(stg + OF_B);

        BFrag fbh[2], fbl[2];
#pragma unroll
        for (int fn = 0; fn < 2; ++fn) {
            wmma::load_matrix_sync(fbh[fn], Bb + wn * 32 + fn * 16, B_LDM);
            wmma::load_matrix_sync(fbl[fn], Bb + 16 * B_LDM + wn * 32 + fn * 16, B_LDM);
        }

        AccFrag (*tgt)[2] = (cc < 32) ? acc : acc2;
#pragma unroll
        for (int fm = 0; fm < 4; ++fm) {
            const int mrow = wm * 64 + fm * 16;
            AFrag fah, fal;
            wmma::load_matrix_sync(fah, Ab + mrow * A_LDM, A_LDM);
            wmma::load_matrix_sync(fal, Ab + 128 * A_LDM + mrow * A_LDM, A_LDM);
#pragma unroll
            for (int fn = 0; fn < 2; ++fn) {
                wmma::mma_sync(tgt[fm][fn], fah, fbh[fn], tgt[fm][fn]);
                wmma::mma_sync(tgt[fm][fn], fah, fbl[fn], tgt[fm][fn]);
                wmma::mma_sync(tgt[fm][fn], fal, fbh[fn], tgt[fm][fn]);
            }
        }

        if (cc == 15) {          // end of pass0: acc2 = P1
#pragma unroll
            for (int fm = 0; fm < 4; ++fm)
#pragma unroll
                for (int fn = 0; fn < 2; ++fn)
#pragma unroll
                    for (int e = 0; e < 8; ++e)
                        acc2[fm][fn].x[e] = acc[fm][fn].x[e];
        }
        if (cc == 31) {          // end of pass1: acc = Cre
#pragma unroll
            for (int fm = 0; fm < 4; ++fm)
#pragma unroll
                for (int fn = 0; fn < 2; ++fn)
                    wmma::store_matrix_sync(
                        g_Cre + pb + (size_t)(m0 + wm * 64 + fm * 16) * 256 + n0 + wn * 32 + fn * 16,
                        acc[fm][fn], 256, wmma::mem_row_major);
        }
        if (cc + 2 < 48) LOAD_CHUNK((cc + 2) % 3, cc + 2);
    }

    // acc2 = Cim
#pragma unroll
    for (int fm = 0; fm < 4; ++fm)
#pragma unroll
        for (int fn = 0; fn < 2; ++fn)
            wmma::store_matrix_sync(
                g_Cim + pb + (size_t)(m0 + wm * 64 + fm * 16) * 256 + n0 + wn * 32 + fn * 16,
                acc2[fm][fn], 256, wmma::mem_row_major);
}

// ===========================================================================
// Inverse: Hermitian spectrum (planar Cre/Cim) -> real 64 via iFFT32.
// ===========================================================================
__global__ __launch_bounds__(256) void ifft_kernel(float* __restrict__ out)
{
    const int tube = blockIdx.x * 256 + threadIdx.x;
    const int b    = tube >> 16;
    const int in_  = tube & 0xFFFF;

    float zr[32], zi[32];
    const float h = 1.0f / 64.0f;

    {
        const size_t o0  = (((size_t)(b * NF + 0))  << 16) + in_;
        const size_t o32 = (((size_t)(b * NF + 32)) << 16) + in_;
        const float X0r = g_Cre[o0],  X0i = g_Cim[o0];
        const float X2r = g_Cre[o32], X2i = g_Cim[o32];
        const float Er = (X0r + X2r) * h, Ei = (X0i + X2i) * h;
        const float Or = (X0r - X2r) * h, Oi = (X0i - X2i) * h;
        zr[0] = Er - Oi;
        zi[0] = Ei + Or;
    }
#pragma unroll
    for (int k = 1; k <= 16; ++k) {
        const size_t ok = (((size_t)(b * NF + k))        << 16) + in_;
        const size_t oq = (((size_t)(b * NF + (32 - k))) << 16) + in_;
        const float Xkr = g_Cre[ok], Xki = g_Cim[ok];
        const float Xqr = g_Cre[oq], Xqi = g_Cim[oq];
        const float Er = (Xkr + Xqr) * h, Ei = (Xki - Xqi) * h;
        const float Dr = (Xkr - Xqr) * h, Di = (Xki + Xqi) * h;
        const float Or = Dr * W64R[k] - Di * W64I[k];
        const float Oi = Dr * W64I[k] + Di * W64R[k];
        zr[k] = Er - Oi;
        zi[k] = Ei + Or;
        if (k < 16) {
            zr[32 - k] = Er + Oi;
            zi[32 - k] = Or - Ei;
        }
    }

    fft32<1>(zr, zi);

    float* dst = out + (size_t)tube * N3;
#pragma unroll
    for (int n = 0; n < 32; n += 2) {
        const int p0 = BR5[n], p1 = BR5[n + 1];
        *reinterpret_cast<float4*>(dst + 2 * n) =
            make_float4(zr[p0], zi[p0], zr[p1], zi[p1]);
    }
}

// ===========================================================================
extern "C" void kernel_launch(void* const* d_in, const int* in_sizes, int n_in,
                              void* d_out, int out_size)
{
    const float* A = (const float*)d_in[0];
    const float* B = (const float*)d_in[1];
    float* out = (float*)d_out;

    cudaFuncSetAttribute(cgemm_wmma_kernel,
                         cudaFuncAttributeMaxDynamicSharedMemorySize, SMEM_GEMM);

    const int fftBlocks = NTUBES / 128;          // 4096
    fft_fwd_kernel<<<fftBlocks, 128>>>(A, 0);
    fft_fwd_kernel<<<fftBlocks, 128>>>(B, 1);

    dim3 ggrid(2, 2, NFP);                       // (m, n, plane-slowest) 1056 CTAs
    cgemm_wmma_kernel<<<ggrid, 256, SMEM_GEMM>>>();

    ifft_kernel<<<NTUBES / 256, 256>>>(out);
}